// round 1
// baseline (speedup 1.0000x reference)
#include <cuda_runtime.h>
#include <cstdint>

// Problem constants
#define TT 512      // tokens
#define HH 2048     // hidden
#define EE 64       // experts
#define TOPK 8
#define II 768      // moe intermediate
#define CAP 192     // max tokens per expert (mean 64, std 7.5 -> 17 sigma headroom)

typedef unsigned long long ull;

// ---------------- device scratch (static: no allocation allowed) --------------
__device__ int   g_counts[EE];
__device__ int   g_tok[EE * CAP];
__device__ float g_wt[EE * CAP];
__device__ float g_act[(size_t)EE * CAP * II];   // ~37.7 MB routed swiglu activations
__device__ float g_h1[(size_t)TT * II];          // shared-expert swiglu activations

// ---------------- packed f32x2 helpers (Blackwell FFMA2 path) ----------------
__device__ __forceinline__ ull fma2(ull a, ull b, ull c) {
    ull d;
    asm("fma.rn.f32x2 %0, %1, %2, %3;" : "=l"(d) : "l"(a), "l"(b), "l"(c));
    return d;
}
__device__ __forceinline__ ull pack_dup(float x) {
    ull d; unsigned int r = __float_as_uint(x);
    asm("mov.b64 %0, {%1, %1};" : "=l"(d) : "r"(r));
    return d;
}
__device__ __forceinline__ void unpack2(ull v, float& lo, float& hi) {
    unsigned int a, b;
    asm("mov.b64 {%0, %1}, %2;" : "=r"(a), "=r"(b) : "l"(v));
    lo = __uint_as_float(a); hi = __uint_as_float(b);
}
__device__ __forceinline__ float silu(float g) {
    return g / (1.f + __expf(-g));
}

// ---------------- kernel 0: zero per-expert counts ---------------------------
__global__ void zero_counts_kernel() {
    if (threadIdx.x < EE) g_counts[threadIdx.x] = 0;
}

// ---------------- kernel 1: router (sigmoid + bias top-8 + norm) -------------
// one block per token, 256 threads: 4 threads per expert for the H=2048 dot
__global__ void __launch_bounds__(256) router_kernel(
    const float* __restrict__ x,
    const float* __restrict__ gate_w,
    const float* __restrict__ gate_b)
{
    __shared__ float xs[HH];
    __shared__ float score[EE];
    __shared__ float biased[EE];
    int t = blockIdx.x;

    for (int h = threadIdx.x; h < HH; h += 256)
        xs[h] = x[(size_t)t * HH + h];
    __syncthreads();

    int e = threadIdx.x >> 2;       // 0..63
    int q = threadIdx.x & 3;        // 0..3
    const float* gw = gate_w + (size_t)e * HH;
    float acc = 0.f;
    int hbase = q * (HH / 4);
    for (int h = hbase; h < hbase + HH / 4; h += 4) {
        float4 g4 = *(const float4*)(gw + h);
        acc += xs[h] * g4.x + xs[h + 1] * g4.y + xs[h + 2] * g4.z + xs[h + 3] * g4.w;
    }
    // reduce groups of 4 lanes (aligned within warp)
    acc += __shfl_down_sync(0xffffffffu, acc, 2);
    acc += __shfl_down_sync(0xffffffffu, acc, 1);
    if (q == 0) {
        float s = 1.f / (1.f + __expf(-acc));
        score[e]  = s;
        biased[e] = s + gate_b[e];
    }
    __syncthreads();

    if (threadIdx.x == 0) {
        bool used[EE];
        #pragma unroll
        for (int i = 0; i < EE; i++) used[i] = false;
        int   idx[TOPK];
        float w[TOPK];
        float sum = 0.f;
        for (int k = 0; k < TOPK; k++) {
            float best = -1e30f; int bi = 0;
            for (int ee = 0; ee < EE; ee++) {
                if (!used[ee] && biased[ee] > best) { best = biased[ee]; bi = ee; }
            }
            used[bi] = true; idx[k] = bi; w[k] = score[bi]; sum += w[k];
        }
        float inv = 1.f / (sum + 1e-20f);
        for (int k = 0; k < TOPK; k++) {
            int ee = idx[k];
            int slot = atomicAdd(&g_counts[ee], 1);
            if (slot < CAP) {
                g_tok[ee * CAP + slot] = t;
                g_wt[ee * CAP + slot]  = w[k] * inv;
            }
        }
    }
}

// ---------------- GEMM tiling params -----------------------------------------
#define BM 64
#define BN 64
#define BK 16
#define NTHR 256

// ---------------- kernel 2: dual GEMM + SwiGLU -------------------------------
// routed=1: A = x rows gathered per expert (blockIdx.z), B = w_gate/w_up[e],
//           out -> g_act.  routed=0: A = x identity, B = sw_gate/sw_up, out -> g_h1.
__global__ void __launch_bounds__(NTHR) swiglu_gemm_kernel(
    const float* __restrict__ x,
    const float* __restrict__ Wg_base,
    const float* __restrict__ Wu_base,
    int routed)
{
    __shared__ float As[BK][BM + 4];
    __shared__ float Bgs[BK][BN];
    __shared__ float Bus[BK][BN];

    int e  = blockIdx.z;
    int n0 = blockIdx.x * BN;
    int m0 = blockIdx.y * BM;

    int cnt;
    const float *Wg, *Wu;
    if (routed) {
        cnt = min(g_counts[e], CAP);
        if (m0 >= cnt) return;
        Wg = Wg_base + (size_t)e * HH * II;
        Wu = Wu_base + (size_t)e * HH * II;
    } else {
        cnt = TT;
        Wg = Wg_base; Wu = Wu_base;
    }

    int tid  = threadIdx.x;
    int rowA = tid >> 2;            // 0..63
    int cgA  = (tid & 3) * 4;       // k offset 0/4/8/12
    int rowB = tid >> 4;            // 0..15
    int colB = (tid & 15) * 4;

    int mi = m0 + rowA;
    const float* arow = nullptr;
    if (mi < cnt) {
        int tok = routed ? g_tok[e * CAP + mi] : mi;
        arow = x + (size_t)tok * HH;
    }

    int tx = tid & 15;   // n micro-tile
    int ty = tid >> 4;   // m micro-tile

    ull accg[4][2], accu[4][2];
    #pragma unroll
    for (int i = 0; i < 4; i++) { accg[i][0] = 0; accg[i][1] = 0; accu[i][0] = 0; accu[i][1] = 0; }

    for (int k0 = 0; k0 < HH; k0 += BK) {
        float4 a4 = make_float4(0.f, 0.f, 0.f, 0.f);
        if (arow) a4 = *(const float4*)(arow + k0 + cgA);
        As[cgA + 0][rowA] = a4.x;
        As[cgA + 1][rowA] = a4.y;
        As[cgA + 2][rowA] = a4.z;
        As[cgA + 3][rowA] = a4.w;
        *(float4*)&Bgs[rowB][colB] = *(const float4*)(Wg + (size_t)(k0 + rowB) * II + n0 + colB);
        *(float4*)&Bus[rowB][colB] = *(const float4*)(Wu + (size_t)(k0 + rowB) * II + n0 + colB);
        __syncthreads();

        #pragma unroll
        for (int kk = 0; kk < BK; kk++) {
            float4 av = *(const float4*)&As[kk][ty * 4];
            ull a2[4] = { pack_dup(av.x), pack_dup(av.y), pack_dup(av.z), pack_dup(av.w) };
            ulonglong2 bg = *(const ulonglong2*)&Bgs[kk][tx * 4];
            ulonglong2 bu = *(const ulonglong2*)&Bus[kk][tx * 4];
            #pragma unroll
            for (int i = 0; i < 4; i++) {
                accg[i][0] = fma2(a2[i], bg.x, accg[i][0]);
                accg[i][1] = fma2(a2[i], bg.y, accg[i][1]);
                accu[i][0] = fma2(a2[i], bu.x, accu[i][0]);
                accu[i][1] = fma2(a2[i], bu.y, accu[i][1]);
            }
        }
        __syncthreads();
    }

    #pragma unroll
    for (int i = 0; i < 4; i++) {
        int m = m0 + ty * 4 + i;
        if (m >= cnt) continue;
        float g0, g1, g2, g3, u0, u1, u2, u3;
        unpack2(accg[i][0], g0, g1); unpack2(accg[i][1], g2, g3);
        unpack2(accu[i][0], u0, u1); unpack2(accu[i][1], u2, u3);
        float4 r;
        r.x = silu(g0) * u0;
        r.y = silu(g1) * u1;
        r.z = silu(g2) * u2;
        r.w = silu(g3) * u3;
        float* dst = routed
            ? (g_act + ((size_t)(e * CAP + m)) * II + n0 + tx * 4)
            : (g_h1  + (size_t)m * II + n0 + tx * 4);
        *(float4*)dst = r;
    }
}

// ---------------- kernel 3: down projection ----------------------------------
// routed=0: out = g_h1 @ sw_down (plain store, initializes out).
// routed=1: out[tok] += wt * (g_act[e-rows] @ w_down[e])  (atomicAdd).
__global__ void __launch_bounds__(NTHR) down_gemm_kernel(
    const float* __restrict__ Wd_base,
    float* __restrict__ out,
    int routed)
{
    __shared__ float As[BK][BM + 4];
    __shared__ float Bs[BK][BN];

    int e  = blockIdx.z;
    int n0 = blockIdx.x * BN;
    int m0 = blockIdx.y * BM;

    int cnt;
    const float* Wd;
    const float* Abase;
    if (routed) {
        cnt = min(g_counts[e], CAP);
        if (m0 >= cnt) return;
        Wd = Wd_base + (size_t)e * II * HH;
        Abase = g_act + (size_t)e * CAP * II;
    } else {
        cnt = TT;
        Wd = Wd_base;
        Abase = g_h1;
    }

    int tid  = threadIdx.x;
    int rowA = tid >> 2;
    int cgA  = (tid & 3) * 4;
    int rowB = tid >> 4;
    int colB = (tid & 15) * 4;

    int mi = m0 + rowA;
    const float* arow = (mi < cnt) ? (Abase + (size_t)mi * II) : nullptr;

    int tx = tid & 15;
    int ty = tid >> 4;

    ull acc[4][2];
    #pragma unroll
    for (int i = 0; i < 4; i++) { acc[i][0] = 0; acc[i][1] = 0; }

    for (int k0 = 0; k0 < II; k0 += BK) {
        float4 a4 = make_float4(0.f, 0.f, 0.f, 0.f);
        if (arow) a4 = *(const float4*)(arow + k0 + cgA);
        As[cgA + 0][rowA] = a4.x;
        As[cgA + 1][rowA] = a4.y;
        As[cgA + 2][rowA] = a4.z;
        As[cgA + 3][rowA] = a4.w;
        *(float4*)&Bs[rowB][colB] = *(const float4*)(Wd + (size_t)(k0 + rowB) * HH + n0 + colB);
        __syncthreads();

        #pragma unroll
        for (int kk = 0; kk < BK; kk++) {
            float4 av = *(const float4*)&As[kk][ty * 4];
            ull a2[4] = { pack_dup(av.x), pack_dup(av.y), pack_dup(av.z), pack_dup(av.w) };
            ulonglong2 b = *(const ulonglong2*)&Bs[kk][tx * 4];
            #pragma unroll
            for (int i = 0; i < 4; i++) {
                acc[i][0] = fma2(a2[i], b.x, acc[i][0]);
                acc[i][1] = fma2(a2[i], b.y, acc[i][1]);
            }
        }
        __syncthreads();
    }

    #pragma unroll
    for (int i = 0; i < 4; i++) {
        int m = m0 + ty * 4 + i;
        if (m >= cnt) continue;
        float v0, v1, v2, v3;
        unpack2(acc[i][0], v0, v1);
        unpack2(acc[i][1], v2, v3);
        if (routed) {
            int   tok = g_tok[e * CAP + m];
            float w   = g_wt[e * CAP + m];
            float* dst = out + (size_t)tok * HH + n0 + tx * 4;
            atomicAdd(dst + 0, v0 * w);
            atomicAdd(dst + 1, v1 * w);
            atomicAdd(dst + 2, v2 * w);
            atomicAdd(dst + 3, v3 * w);
        } else {
            float* dst = out + (size_t)m * HH + n0 + tx * 4;
            *(float4*)dst = make_float4(v0, v1, v2, v3);
        }
    }
}

// ---------------- launch ------------------------------------------------------
extern "C" void kernel_launch(void* const* d_in, const int* in_sizes, int n_in,
                              void* d_out, int out_size)
{
    const float* x       = (const float*)d_in[0];
    const float* gate_w  = (const float*)d_in[1];
    const float* gate_b  = (const float*)d_in[2];
    const float* w_gate  = (const float*)d_in[3];
    const float* w_up    = (const float*)d_in[4];
    const float* w_down  = (const float*)d_in[5];
    const float* sw_gate = (const float*)d_in[6];
    const float* sw_up   = (const float*)d_in[7];
    const float* sw_down = (const float*)d_in[8];
    float* out = (float*)d_out;

    // 0) reset routing scratch
    zero_counts_kernel<<<1, 64>>>();

    // 1) router: per-token top-8 + per-expert token lists
    router_kernel<<<TT, 256>>>(x, gate_w, gate_b);

    // 2) shared expert swiglu: g_h1 = silu(x@sw_gate)*(x@sw_up)
    swiglu_gemm_kernel<<<dim3(II / BN, TT / BM, 1), NTHR>>>(x, sw_gate, sw_up, 0);

    // 3) shared expert down: out = g_h1 @ sw_down (initializes out)
    down_gemm_kernel<<<dim3(HH / BN, TT / BM, 1), NTHR>>>(sw_down, out, 0);

    // 4) routed swiglu per expert: g_act = silu(Xe@Wg[e]) * (Xe@Wu[e])
    swiglu_gemm_kernel<<<dim3(II / BN, CAP / BM, EE), NTHR>>>(x, w_gate, w_up, 1);

    // 5) routed down: out[tok] += wt * (g_act @ w_down[e])
    down_gemm_kernel<<<dim3(HH / BN, CAP / BM, EE), NTHR>>>(w_down, out, 1);
}

// round 4
// speedup vs baseline: 2.0274x; 2.0274x over previous
#include <cuda_runtime.h>
#include <cstdint>

// ---------------- problem constants ----------------
#define TT 512      // tokens
#define HH 2048     // hidden
#define EE 64       // experts
#define TOPK 8
#define II 768      // moe intermediate
#define CAP 192     // max tokens per expert

// ---------------- tiling ----------------
#define MT 64       // CTA M tile
#define NT 128      // CTA N tile
#define BK 32       // K per chunk
#define NTHR 256    // 8 warps, 2(m) x 4(n), warp tile 32x32

#define LDA 36      // A smem stride (floats): bank = 4g+t (conflict-free)
#define LDB 136     // B smem stride (floats): bank = 8t+g (conflict-free)
#define A_BYTES (MT * LDA * 4)            // 9216
#define B_BYTES (BK * LDB * 4)            // 17408
#define SW_STAGE (A_BYTES + 2 * B_BYTES)  // 44032 (A + Bg + Bu)
#define SW_SMEM  (2 * SW_STAGE)           // 88064
#define DN_STAGE (A_BYTES + B_BYTES)      // 26624
#define DN_SMEM  (2 * DN_STAGE)           // 53248

// ---------------- device scratch (static; no allocation allowed) -------------
__device__ int   g_counts[EE];
__device__ int   g_tok[EE * CAP];
__device__ float g_wt[EE * CAP];
// swiglu activations: rows [0, EE*CAP) routed (slot-indexed), [EE*CAP, +TT) shared
__device__ float g_act[(size_t)(EE * CAP + TT) * II];

// ---------------- PTX helpers -------------------------------------------------
__device__ __forceinline__ uint32_t smem_u32(const void* p) {
    uint32_t a;
    asm("{ .reg .u64 t; cvta.to.shared.u64 t, %1; cvt.u32.u64 %0, t; }"
        : "=r"(a) : "l"(p));
    return a;
}
__device__ __forceinline__ void cp16(uint32_t dst, const float* src, int sz) {
    asm volatile("cp.async.cg.shared.global [%0], [%1], 16, %2;"
                 :: "r"(dst), "l"(src), "r"(sz) : "memory");
}
__device__ __forceinline__ void cp_commit() {
    asm volatile("cp.async.commit_group;" ::: "memory");
}
__device__ __forceinline__ void cp_wait1() {
    asm volatile("cp.async.wait_group 1;" ::: "memory");
}
// round fp32 -> tf32 (round-to-nearest; removes the HMMA truncation bias)
__device__ __forceinline__ uint32_t tf32r(float f) {
    uint32_t u;
    asm("cvt.rna.tf32.f32 %0, %1;" : "=r"(u) : "f"(f));
    return u;
}
__device__ __forceinline__ void mma8(float c[4], const uint32_t a[4], const uint32_t b[2]) {
    asm volatile(
        "mma.sync.aligned.m16n8k8.row.col.f32.tf32.tf32.f32 "
        "{%0,%1,%2,%3}, {%4,%5,%6,%7}, {%8,%9}, {%0,%1,%2,%3};"
        : "+f"(c[0]), "+f"(c[1]), "+f"(c[2]), "+f"(c[3])
        : "r"(a[0]), "r"(a[1]), "r"(a[2]), "r"(a[3]), "r"(b[0]), "r"(b[1]));
}
__device__ __forceinline__ float silu(float g) { return g / (1.f + __expf(-g)); }

// ============================================================================
// kernel 0: zero per-expert counts
// ============================================================================
__global__ void zero_counts_kernel() {
    if (threadIdx.x < EE) g_counts[threadIdx.x] = 0;
}

// ============================================================================
// kernel 1: router (fp32 exact): sigmoid + biased top-8 + normalize
// ============================================================================
__global__ void __launch_bounds__(256) router_kernel(
    const float* __restrict__ x,
    const float* __restrict__ gate_w,
    const float* __restrict__ gate_b)
{
    __shared__ float xs[HH];
    __shared__ float score[EE];
    __shared__ float biased[EE];
    int t = blockIdx.x;

    for (int h = threadIdx.x; h < HH; h += 256)
        xs[h] = x[(size_t)t * HH + h];
    __syncthreads();

    int e = threadIdx.x >> 2;
    int q = threadIdx.x & 3;
    const float* gw = gate_w + (size_t)e * HH;
    float acc = 0.f;
    int hbase = q * (HH / 4);
    for (int h = hbase; h < hbase + HH / 4; h += 4) {
        float4 g4 = *(const float4*)(gw + h);
        acc += xs[h] * g4.x + xs[h + 1] * g4.y + xs[h + 2] * g4.z + xs[h + 3] * g4.w;
    }
    acc += __shfl_down_sync(0xffffffffu, acc, 2);
    acc += __shfl_down_sync(0xffffffffu, acc, 1);
    if (q == 0) {
        float s = 1.f / (1.f + __expf(-acc));
        score[e]  = s;
        biased[e] = s + gate_b[e];
    }
    __syncthreads();

    if (threadIdx.x == 0) {
        bool used[EE];
        #pragma unroll
        for (int i = 0; i < EE; i++) used[i] = false;
        int   idx[TOPK];
        float w[TOPK];
        float sum = 0.f;
        for (int k = 0; k < TOPK; k++) {
            float best = -1e30f; int bi = 0;
            for (int ee = 0; ee < EE; ee++)
                if (!used[ee] && biased[ee] > best) { best = biased[ee]; bi = ee; }
            used[bi] = true; idx[k] = bi; w[k] = score[bi]; sum += w[k];
        }
        float inv = 1.f / (sum + 1e-20f);
        for (int k = 0; k < TOPK; k++) {
            int ee = idx[k];
            int slot = atomicAdd(&g_counts[ee], 1);
            if (slot < CAP) {
                g_tok[ee * CAP + slot] = t;
                g_wt[ee * CAP + slot]  = w[k] * inv;
            }
        }
    }
}

// ============================================================================
// kernel 2: SwiGLU dual-B GEMM via mma.sync tf32
//   z < EE: routed expert e (A = gathered x rows), z == EE: shared expert.
//   C_g = A @ Wg, C_u = A @ Wu; epilogue: act = tf32(silu(g)*u) -> g_act.
// ============================================================================
__global__ void __launch_bounds__(NTHR, 2) swiglu_kernel(
    const float* __restrict__ x,
    const float* __restrict__ w_gate, const float* __restrict__ w_up,
    const float* __restrict__ sw_gate, const float* __restrict__ sw_up)
{
    extern __shared__ char sm[];
    int e = blockIdx.z;
    bool se = (e == EE);
    int cnt;
    const float *Wg, *Wu;
    if (se) { cnt = TT; Wg = sw_gate; Wu = sw_up; }
    else {
        cnt = min(g_counts[e], CAP);
        Wg = w_gate + (size_t)e * HH * II;
        Wu = w_up   + (size_t)e * HH * II;
    }
    int m0 = blockIdx.y * MT;
    if (m0 >= cnt) return;
    int n0 = blockIdx.x * NT;

    int tid  = threadIdx.x;
    int lane = tid & 31, warp = tid >> 5;
    int qg = lane >> 2, qt = lane & 3;      // quad row / quad col
    int wm = warp >> 2, wn = warp & 3;      // warp grid 2 x 4

    uint32_t smb = smem_u32(sm);

    // ---- A-load assignment: 64 rows x 32 floats = 512 x 16B, 2 per thread ----
    int ar  = tid >> 3;          // 0..31 (rows tid and tid+32 handled)
    int ac  = tid & 7;           // 16B slot within 32-float row
    int gm0 = m0 + ar, gm1 = m0 + ar + 32;
    int v0 = (gm0 < cnt) ? 16 : 0;
    int v1 = (gm1 < cnt) ? 16 : 0;
    int tok0 = se ? gm0 : (v0 ? g_tok[e * CAP + gm0] : 0);
    int tok1 = se ? gm1 : (v1 ? g_tok[e * CAP + gm1] : 0);
    const float* as0 = x + (size_t)tok0 * HH + ac * 4;
    const float* as1 = x + (size_t)tok1 * HH + ac * 4;
    uint32_t ad0 = ar * 144 + ac * 16;
    uint32_t ad1 = (ar + 32) * 144 + ac * 16;

    // ---- B-load assignment: 32 rows x 128 floats = 1024 x 16B, 4 per thread per matrix
    int brow = tid >> 5;         // + 8*j
    int bc   = tid & 31;

    const int NC = HH / BK;      // 64 chunks

    // prefetch chunk c into stage c&1
    auto prefetch = [&](int c) {
        int k0 = c * BK;
        uint32_t st = smb + (uint32_t)(c & 1) * SW_STAGE;
        cp16(st + ad0, as0 + k0, v0);
        cp16(st + ad1, as1 + k0, v1);
        uint32_t bg = st + A_BYTES, bu = bg + B_BYTES;
        #pragma unroll
        for (int j = 0; j < 4; j++) {
            int r = brow + 8 * j;
            cp16(bg + r * 544 + bc * 16, Wg + (size_t)(k0 + r) * II + n0 + bc * 4, 16);
            cp16(bu + r * 544 + bc * 16, Wu + (size_t)(k0 + r) * II + n0 + bc * 4, 16);
        }
        cp_commit();
    };

    float cg[2][4][4], cu[2][4][4];
    #pragma unroll
    for (int mi = 0; mi < 2; mi++)
        #pragma unroll
        for (int ni = 0; ni < 4; ni++)
            #pragma unroll
            for (int r = 0; r < 4; r++) { cg[mi][ni][r] = 0.f; cu[mi][ni][r] = 0.f; }

    prefetch(0);
    prefetch(1);

    for (int c = 0; c < NC; c++) {
        cp_wait1();
        __syncthreads();
        const float* As = (const float*)(sm + (size_t)(c & 1) * SW_STAGE);
        const float* Bg = As + A_BYTES / 4;
        const float* Bu = Bg + B_BYTES / 4;

        #pragma unroll
        for (int kk = 0; kk < 4; kk++) {
            int kb = kk * 8;
            uint32_t a[2][4];
            #pragma unroll
            for (int mi = 0; mi < 2; mi++) {
                int r = wm * 32 + mi * 16 + qg;
                a[mi][0] = tf32r(As[(size_t)r * LDA + kb + qt]);
                a[mi][1] = tf32r(As[(size_t)(r + 8) * LDA + kb + qt]);
                a[mi][2] = tf32r(As[(size_t)r * LDA + kb + qt + 4]);
                a[mi][3] = tf32r(As[(size_t)(r + 8) * LDA + kb + qt + 4]);
            }
            uint32_t bgf[4][2], buf2[4][2];
            #pragma unroll
            for (int ni = 0; ni < 4; ni++) {
                int cc = wn * 32 + ni * 8 + qg;
                bgf[ni][0]  = tf32r(Bg[(size_t)(kb + qt) * LDB + cc]);
                bgf[ni][1]  = tf32r(Bg[(size_t)(kb + qt + 4) * LDB + cc]);
                buf2[ni][0] = tf32r(Bu[(size_t)(kb + qt) * LDB + cc]);
                buf2[ni][1] = tf32r(Bu[(size_t)(kb + qt + 4) * LDB + cc]);
            }
            #pragma unroll
            for (int mi = 0; mi < 2; mi++)
                #pragma unroll
                for (int ni = 0; ni < 4; ni++) {
                    mma8(cg[mi][ni], a[mi], bgf[ni]);
                    mma8(cu[mi][ni], a[mi], buf2[ni]);
                }
        }
        __syncthreads();
        if (c + 2 < NC) prefetch(c + 2);
        else cp_commit();   // empty group keeps wait_group(1) semantics correct
    }

    // ---- epilogue: act = tf32(silu(g) * u) -> g_act ----
    size_t Rbase = se ? (size_t)EE * CAP : (size_t)e * CAP;
    #pragma unroll
    for (int mi = 0; mi < 2; mi++) {
        #pragma unroll
        for (int ni = 0; ni < 4; ni++) {
            int col = n0 + wn * 32 + ni * 8 + qt * 2;
            #pragma unroll
            for (int h = 0; h < 2; h++) {
                int m = m0 + wm * 32 + mi * 16 + qg + 8 * h;
                if (m < cnt) {
                    float gv0 = cg[mi][ni][2 * h], gv1 = cg[mi][ni][2 * h + 1];
                    float uv0 = cu[mi][ni][2 * h], uv1 = cu[mi][ni][2 * h + 1];
                    float2 o;
                    o.x = __uint_as_float(tf32r(silu(gv0) * uv0));
                    o.y = __uint_as_float(tf32r(silu(gv1) * uv1));
                    *(float2*)(g_act + (Rbase + m) * II + col) = o;
                }
            }
        }
    }
}

// ============================================================================
// kernel 3: down-projection GEMM via mma.sync tf32
//   routed == 0: shared expert, plain store (initializes all of out).
//   routed == 1: per-expert, out[tok] += wt * C (atomicAdd).
// ============================================================================
__global__ void __launch_bounds__(NTHR, 2) down_kernel(
    const float* __restrict__ w_down,
    const float* __restrict__ sw_down,
    float* __restrict__ out,
    int routed)
{
    extern __shared__ char sm[];
    int e = blockIdx.z;
    int cnt;
    const float* Wd;
    size_t Rbase;
    if (routed) {
        cnt = min(g_counts[e], CAP);
        Wd = w_down + (size_t)e * II * HH;
        Rbase = (size_t)e * CAP;
    } else {
        cnt = TT;
        Wd = sw_down;
        Rbase = (size_t)EE * CAP;
    }
    int m0 = blockIdx.y * MT;
    if (m0 >= cnt) return;
    int n0 = blockIdx.x * NT;

    int tid  = threadIdx.x;
    int lane = tid & 31, warp = tid >> 5;
    int qg = lane >> 2, qt = lane & 3;
    int wm = warp >> 2, wn = warp & 3;

    uint32_t smb = smem_u32(sm);

    int ar = tid >> 3, ac = tid & 7;
    int v0 = (m0 + ar < cnt) ? 16 : 0;
    int v1 = (m0 + ar + 32 < cnt) ? 16 : 0;
    const float* as0 = g_act + (Rbase + m0 + ar) * II + ac * 4;
    const float* as1 = g_act + (Rbase + m0 + ar + 32) * II + ac * 4;
    uint32_t ad0 = ar * 144 + ac * 16;
    uint32_t ad1 = (ar + 32) * 144 + ac * 16;

    int brow = tid >> 5, bc = tid & 31;

    const int NC = II / BK;      // 24 chunks

    auto prefetch = [&](int c) {
        int k0 = c * BK;
        uint32_t st = smb + (uint32_t)(c & 1) * DN_STAGE;
        cp16(st + ad0, as0 + k0, v0);
        cp16(st + ad1, as1 + k0, v1);
        uint32_t bb = st + A_BYTES;
        #pragma unroll
        for (int j = 0; j < 4; j++) {
            int r = brow + 8 * j;
            cp16(bb + r * 544 + bc * 16, Wd + (size_t)(k0 + r) * HH + n0 + bc * 4, 16);
        }
        cp_commit();
    };

    float cc[2][4][4];
    #pragma unroll
    for (int mi = 0; mi < 2; mi++)
        #pragma unroll
        for (int ni = 0; ni < 4; ni++)
            #pragma unroll
            for (int r = 0; r < 4; r++) cc[mi][ni][r] = 0.f;

    prefetch(0);
    prefetch(1);

    for (int c = 0; c < NC; c++) {
        cp_wait1();
        __syncthreads();
        const float* As = (const float*)(sm + (size_t)(c & 1) * DN_STAGE);
        const float* Bs = As + A_BYTES / 4;

        #pragma unroll
        for (int kk = 0; kk < 4; kk++) {
            int kb = kk * 8;
            uint32_t a[2][4];
            #pragma unroll
            for (int mi = 0; mi < 2; mi++) {
                int r = wm * 32 + mi * 16 + qg;
                a[mi][0] = tf32r(As[(size_t)r * LDA + kb + qt]);
                a[mi][1] = tf32r(As[(size_t)(r + 8) * LDA + kb + qt]);
                a[mi][2] = tf32r(As[(size_t)r * LDA + kb + qt + 4]);
                a[mi][3] = tf32r(As[(size_t)(r + 8) * LDA + kb + qt + 4]);
            }
            uint32_t b[4][2];
            #pragma unroll
            for (int ni = 0; ni < 4; ni++) {
                int col = wn * 32 + ni * 8 + qg;
                b[ni][0] = tf32r(Bs[(size_t)(kb + qt) * LDB + col]);
                b[ni][1] = tf32r(Bs[(size_t)(kb + qt + 4) * LDB + col]);
            }
            #pragma unroll
            for (int mi = 0; mi < 2; mi++)
                #pragma unroll
                for (int ni = 0; ni < 4; ni++)
                    mma8(cc[mi][ni], a[mi], b[ni]);
        }
        __syncthreads();
        if (c + 2 < NC) prefetch(c + 2);
        else cp_commit();
    }

    // ---- epilogue ----
    #pragma unroll
    for (int mi = 0; mi < 2; mi++) {
        #pragma unroll
        for (int h = 0; h < 2; h++) {
            int m = m0 + wm * 32 + mi * 16 + qg + 8 * h;
            if (m >= cnt) continue;
            int tok;
            float wt = 1.f;
            if (routed) { tok = g_tok[e * CAP + m]; wt = g_wt[e * CAP + m]; }
            else        { tok = m; }
            float* dst = out + (size_t)tok * HH;
            #pragma unroll
            for (int ni = 0; ni < 4; ni++) {
                int col = n0 + wn * 32 + ni * 8 + qt * 2;
                float v0f = cc[mi][ni][2 * h];
                float v1f = cc[mi][ni][2 * h + 1];
                if (routed) {
                    atomicAdd(dst + col,     v0f * wt);
                    atomicAdd(dst + col + 1, v1f * wt);
                } else {
                    *(float2*)(dst + col) = make_float2(v0f, v1f);
                }
            }
        }
    }
}

// ============================================================================
// launch
// ============================================================================
extern "C" void kernel_launch(void* const* d_in, const int* in_sizes, int n_in,
                              void* d_out, int out_size)
{
    const float* x       = (const float*)d_in[0];
    const float* gate_w  = (const float*)d_in[1];
    const float* gate_b  = (const float*)d_in[2];
    const float* w_gate  = (const float*)d_in[3];
    const float* w_up    = (const float*)d_in[4];
    const float* w_down  = (const float*)d_in[5];
    const float* sw_gate = (const float*)d_in[6];
    const float* sw_up   = (const float*)d_in[7];
    const float* sw_down = (const float*)d_in[8];
    float* out = (float*)d_out;

    // host-side, non-stream API: idempotent, executes immediately (capture-safe)
    cudaFuncSetAttribute(swiglu_kernel, cudaFuncAttributeMaxDynamicSharedMemorySize, SW_SMEM);
    cudaFuncSetAttribute(down_kernel,   cudaFuncAttributeMaxDynamicSharedMemorySize, DN_SMEM);

    zero_counts_kernel<<<1, 64>>>();
    router_kernel<<<TT, 256>>>(x, gate_w, gate_b);

    // routed experts (z<64) + shared expert (z==64); y tiles: routed <=3 used, shared 8
    swiglu_kernel<<<dim3(II / NT, TT / MT, EE + 1), NTHR, SW_SMEM>>>(
        x, w_gate, w_up, sw_gate, sw_up);

    // shared expert down first (dense store initializes out) ...
    down_kernel<<<dim3(HH / NT, TT / MT, 1), NTHR, DN_SMEM>>>(w_down, sw_down, out, 0);
    // ... then routed experts accumulate on top
    down_kernel<<<dim3(HH / NT, CAP / MT, EE), NTHR, DN_SMEM>>>(w_down, sw_down, out, 1);
}

// round 6
// speedup vs baseline: 2.5510x; 1.2583x over previous
#include <cuda_runtime.h>
#include <cstdint>

// ---------------- problem constants ----------------
#define TT 512      // tokens
#define HH 2048     // hidden
#define EE 64       // experts
#define TOPK 8
#define II 768      // moe intermediate
#define CAP 192     // max tokens per expert

#define MT 64       // CTA M tile
#define NT 128      // CTA N tile
#define NTHR 256    // 8 warps: 2(m) x 4(n), warp tile 32x32

// swiglu: BK=16, dual-B
#define SW_BK 16
#define SW_LDA 20                          // floats; conflict-free (20*qg+qt)
#define SW_ASZ (MT * SW_LDA * 4)           // 5120 B
#define SW_BSZ (SW_BK * 136 * 4)           // 8704 B
#define SW_STAGE (SW_ASZ + 2 * SW_BSZ)     // 22528 B
#define SW_SMEM (2 * SW_STAGE)             // 45056 B

// down: BK=32, single-B
#define DN_BK 32
#define DN_LDA 36                          // floats; conflict-free (4r+qt)
#define DN_ASZ (MT * DN_LDA * 4)           // 9216 B
#define DN_BSZ (DN_BK * 136 * 4)           // 17408 B
#define DN_STAGE (DN_ASZ + DN_BSZ)         // 26624 B
#define DN_SMEM (2 * DN_STAGE)             // 53248 B

// ---------------- device scratch (static; no allocation allowed) -------------
__device__ int   g_counts[EE];
__device__ int   g_tok[EE * CAP];
__device__ float g_wt[EE * CAP];
// swiglu activations: rows [0, EE*CAP) routed (slot-indexed), [EE*CAP, +TT) shared
__device__ float g_act[(size_t)(EE * CAP + TT) * II];

// ---------------- PTX helpers -------------------------------------------------
__device__ __forceinline__ uint32_t smem_u32(const void* p) {
    uint32_t a;
    asm("{ .reg .u64 t; cvta.to.shared.u64 t, %1; cvt.u32.u64 %0, t; }"
        : "=r"(a) : "l"(p));
    return a;
}
// round fp32 -> tf32 (round-to-nearest; removes the HMMA truncation bias)
__device__ __forceinline__ uint32_t tf32r(float f) {
    uint32_t u;
    asm("cvt.rna.tf32.f32 %0, %1;" : "=r"(u) : "f"(f));
    return u;
}
__device__ __forceinline__ void sts128u(uint32_t addr, uint32_t a, uint32_t b,
                                        uint32_t c, uint32_t d) {
    asm volatile("st.shared.v4.b32 [%0], {%1,%2,%3,%4};"
                 :: "r"(addr), "r"(a), "r"(b), "r"(c), "r"(d) : "memory");
}
__device__ __forceinline__ void mma8(float c[4], const uint32_t a[4], const uint32_t b[2]) {
    asm volatile(
        "mma.sync.aligned.m16n8k8.row.col.f32.tf32.tf32.f32 "
        "{%0,%1,%2,%3}, {%4,%5,%6,%7}, {%8,%9}, {%0,%1,%2,%3};"
        : "+f"(c[0]), "+f"(c[1]), "+f"(c[2]), "+f"(c[3])
        : "r"(a[0]), "r"(a[1]), "r"(a[2]), "r"(a[3]), "r"(b[0]), "r"(b[1]));
}
__device__ __forceinline__ float silu(float g) { return g / (1.f + __expf(-g)); }

// ============================================================================
// kernel 0: zero per-expert counts
// ============================================================================
__global__ void zero_counts_kernel() {
    if (threadIdx.x < EE) g_counts[threadIdx.x] = 0;
}

// ============================================================================
// kernel 1: router, 4 tokens per block (4x less gate_w L2 traffic)
// ============================================================================
__global__ void __launch_bounds__(256) router_kernel(
    const float* __restrict__ x,
    const float* __restrict__ gate_w,
    const float* __restrict__ gate_b)
{
    __shared__ float xs[4][HH];
    __shared__ float score[4][EE];
    __shared__ float biased[4][EE];
    int t0 = blockIdx.x * 4;
    int tid = threadIdx.x;

    for (int i = tid; i < 4 * HH; i += 256)
        xs[i >> 11][i & (HH - 1)] = x[(size_t)t0 * HH + i];
    __syncthreads();

    int e = tid >> 2;
    int q = tid & 3;
    const float* gw = gate_w + (size_t)e * HH;
    float a0 = 0.f, a1 = 0.f, a2 = 0.f, a3 = 0.f;
    for (int h = q * (HH / 4); h < (q + 1) * (HH / 4); h += 4) {
        float4 g4 = *(const float4*)(gw + h);
        a0 += xs[0][h] * g4.x + xs[0][h+1] * g4.y + xs[0][h+2] * g4.z + xs[0][h+3] * g4.w;
        a1 += xs[1][h] * g4.x + xs[1][h+1] * g4.y + xs[1][h+2] * g4.z + xs[1][h+3] * g4.w;
        a2 += xs[2][h] * g4.x + xs[2][h+1] * g4.y + xs[2][h+2] * g4.z + xs[2][h+3] * g4.w;
        a3 += xs[3][h] * g4.x + xs[3][h+1] * g4.y + xs[3][h+2] * g4.z + xs[3][h+3] * g4.w;
    }
    a0 += __shfl_down_sync(~0u, a0, 2); a0 += __shfl_down_sync(~0u, a0, 1);
    a1 += __shfl_down_sync(~0u, a1, 2); a1 += __shfl_down_sync(~0u, a1, 1);
    a2 += __shfl_down_sync(~0u, a2, 2); a2 += __shfl_down_sync(~0u, a2, 1);
    a3 += __shfl_down_sync(~0u, a3, 2); a3 += __shfl_down_sync(~0u, a3, 1);
    if (q == 0) {
        float b = gate_b[e];
        float s0 = 1.f / (1.f + __expf(-a0));
        float s1 = 1.f / (1.f + __expf(-a1));
        float s2 = 1.f / (1.f + __expf(-a2));
        float s3 = 1.f / (1.f + __expf(-a3));
        score[0][e] = s0; biased[0][e] = s0 + b;
        score[1][e] = s1; biased[1][e] = s1 + b;
        score[2][e] = s2; biased[2][e] = s2 + b;
        score[3][e] = s3; biased[3][e] = s3 + b;
    }
    __syncthreads();

    if (tid < 4) {
        int t = t0 + tid;
        bool used[EE];
        #pragma unroll
        for (int i = 0; i < EE; i++) used[i] = false;
        int   idx[TOPK];
        float w[TOPK];
        float sum = 0.f;
        for (int k = 0; k < TOPK; k++) {
            float best = -1e30f; int bi = 0;
            for (int ee = 0; ee < EE; ee++)
                if (!used[ee] && biased[tid][ee] > best) { best = biased[tid][ee]; bi = ee; }
            used[bi] = true; idx[k] = bi; w[k] = score[tid][bi]; sum += w[k];
        }
        float inv = 1.f / (sum + 1e-20f);
        for (int k = 0; k < TOPK; k++) {
            int ee = idx[k];
            int slot = atomicAdd(&g_counts[ee], 1);
            if (slot < CAP) {
                g_tok[ee * CAP + slot] = t;
                g_wt[ee * CAP + slot]  = w[k] * inv;
            }
        }
    }
}

// ============================================================================
// kernel 2: SwiGLU dual-B GEMM, pre-rounded tf32 smem tiles, reg-staged pipeline
// ============================================================================
__global__ void __launch_bounds__(NTHR, 2) swiglu_kernel(
    const float* __restrict__ x,
    const float* __restrict__ w_gate, const float* __restrict__ w_up,
    const float* __restrict__ sw_gate, const float* __restrict__ sw_up)
{
    extern __shared__ char sm[];
    int e = blockIdx.z;
    bool se = (e == EE);
    int cnt;
    const float *Wg, *Wu;
    if (se) { cnt = TT; Wg = sw_gate; Wu = sw_up; }
    else {
        cnt = min(g_counts[e], CAP);
        Wg = w_gate + (size_t)e * HH * II;
        Wu = w_up   + (size_t)e * HH * II;
    }
    int m0 = blockIdx.y * MT;
    if (m0 >= cnt) return;
    int n0 = blockIdx.x * NT;

    int tid  = threadIdx.x;
    int lane = tid & 31, warp = tid >> 5;
    int qg = lane >> 2, qt = lane & 3;
    int wm = warp >> 2, wn = warp & 3;

    uint32_t smb = smem_u32(sm);

    // producer A: row = tid&63, c4 = tid>>6 (4 floats per thread per chunk)
    int ar  = tid & 63;
    int ac4 = tid >> 6;
    int gm  = m0 + ar;
    bool av = (gm < cnt);
    const float* aptr = x;
    if (av) {
        int tok = se ? gm : g_tok[e * CAP + gm];
        aptr = x + (size_t)tok * HH + ac4 * 4;
    }
    uint32_t asts = (uint32_t)(ar * (SW_LDA * 4) + ac4 * 16);

    // producer B: row = tid>>4 (0..15), c4 = tid&15 (+16 for j=1)
    int br  = tid >> 4;
    int bc4 = tid & 15;
    const float* gptr = Wg + (size_t)br * II + n0 + bc4 * 4;
    const float* uptr = Wu + (size_t)br * II + n0 + bc4 * 4;
    uint32_t bsts0 = (uint32_t)(br * 544 + bc4 * 16);
    uint32_t bsts1 = bsts0 + 256;     // +16 vec4 = +64 floats

    const int NC = HH / SW_BK;        // 128 chunks

    float4 rA, rG0, rG1, rU0, rU1;
    auto ldg = [&](int c) {
        size_t ko = (size_t)c * SW_BK;
        rA = av ? *(const float4*)(aptr + ko) : make_float4(0.f, 0.f, 0.f, 0.f);
        const float* g = gptr + ko * II;
        const float* u = uptr + ko * II;
        rG0 = *(const float4*)(g);
        rG1 = *(const float4*)(g + 64);
        rU0 = *(const float4*)(u);
        rU1 = *(const float4*)(u + 64);
    };
    auto sts = [&](int c) {
        uint32_t st = smb + (uint32_t)(c & 1) * SW_STAGE;
        sts128u(st + asts, tf32r(rA.x), tf32r(rA.y), tf32r(rA.z), tf32r(rA.w));
        uint32_t bg = st + SW_ASZ, bu = bg + SW_BSZ;
        sts128u(bg + bsts0, tf32r(rG0.x), tf32r(rG0.y), tf32r(rG0.z), tf32r(rG0.w));
        sts128u(bg + bsts1, tf32r(rG1.x), tf32r(rG1.y), tf32r(rG1.z), tf32r(rG1.w));
        sts128u(bu + bsts0, tf32r(rU0.x), tf32r(rU0.y), tf32r(rU0.z), tf32r(rU0.w));
        sts128u(bu + bsts1, tf32r(rU1.x), tf32r(rU1.y), tf32r(rU1.z), tf32r(rU1.w));
    };

    float cg[2][4][4], cu[2][4][4];
    #pragma unroll
    for (int mi = 0; mi < 2; mi++)
        #pragma unroll
        for (int ni = 0; ni < 4; ni++)
            #pragma unroll
            for (int r = 0; r < 4; r++) { cg[mi][ni][r] = 0.f; cu[mi][ni][r] = 0.f; }

    ldg(0);
    for (int c = 0; c < NC; c++) {
        __syncthreads();
        sts(c);
        __syncthreads();
        if (c + 1 < NC) ldg(c + 1);

        const uint32_t* As = (const uint32_t*)(sm + (size_t)(c & 1) * SW_STAGE);
        const uint32_t* Bg = As + SW_ASZ / 4;
        const uint32_t* Bu = Bg + SW_BSZ / 4;

        #pragma unroll
        for (int kk = 0; kk < 2; kk++) {
            int kb = kk * 8;
            uint32_t a[2][4];
            #pragma unroll
            for (int mi = 0; mi < 2; mi++) {
                int r = wm * 32 + mi * 16 + qg;
                a[mi][0] = As[r * SW_LDA + kb + qt];
                a[mi][1] = As[(r + 8) * SW_LDA + kb + qt];
                a[mi][2] = As[r * SW_LDA + kb + qt + 4];
                a[mi][3] = As[(r + 8) * SW_LDA + kb + qt + 4];
            }
            uint32_t bgf[4][2], buf2[4][2];
            #pragma unroll
            for (int ni = 0; ni < 4; ni++) {
                int cc = wn * 32 + ni * 8 + qg;
                bgf[ni][0]  = Bg[(kb + qt) * 136 + cc];
                bgf[ni][1]  = Bg[(kb + qt + 4) * 136 + cc];
                buf2[ni][0] = Bu[(kb + qt) * 136 + cc];
                buf2[ni][1] = Bu[(kb + qt + 4) * 136 + cc];
            }
            #pragma unroll
            for (int mi = 0; mi < 2; mi++)
                #pragma unroll
                for (int ni = 0; ni < 4; ni++) {
                    mma8(cg[mi][ni], a[mi], bgf[ni]);
                    mma8(cu[mi][ni], a[mi], buf2[ni]);
                }
        }
    }

    // ---- epilogue: act = tf32(silu(g) * u) -> g_act (pre-rounded for down) ----
    size_t Rbase = se ? (size_t)EE * CAP : (size_t)e * CAP;
    #pragma unroll
    for (int mi = 0; mi < 2; mi++) {
        #pragma unroll
        for (int ni = 0; ni < 4; ni++) {
            int col = n0 + wn * 32 + ni * 8 + qt * 2;
            #pragma unroll
            for (int h = 0; h < 2; h++) {
                int m = m0 + wm * 32 + mi * 16 + qg + 8 * h;
                if (m < cnt) {
                    float gv0 = cg[mi][ni][2 * h], gv1 = cg[mi][ni][2 * h + 1];
                    float uv0 = cu[mi][ni][2 * h], uv1 = cu[mi][ni][2 * h + 1];
                    float2 o;
                    o.x = __uint_as_float(tf32r(silu(gv0) * uv0));
                    o.y = __uint_as_float(tf32r(silu(gv1) * uv1));
                    *(float2*)(g_act + (Rbase + m) * II + col) = o;
                }
            }
        }
    }
}

// ============================================================================
// kernel 3: down-projection (routed z<64 + shared z==64), atomicAdd into zeroed out
//   A (g_act) is already tf32-rounded: no cvt anywhere on the A path.
// ============================================================================
__global__ void __launch_bounds__(NTHR, 2) down_kernel(
    const float* __restrict__ w_down,
    const float* __restrict__ sw_down,
    float* __restrict__ out)
{
    extern __shared__ char sm[];
    int e = blockIdx.z;
    bool se = (e == EE);
    int cnt;
    const float* Wd;
    size_t Rbase;
    if (se) { cnt = TT; Wd = sw_down; Rbase = (size_t)EE * CAP; }
    else {
        cnt = min(g_counts[e], CAP);
        Wd = w_down + (size_t)e * II * HH;
        Rbase = (size_t)e * CAP;
    }
    int m0 = blockIdx.y * MT;
    if (m0 >= cnt) return;
    int n0 = blockIdx.x * NT;

    int tid  = threadIdx.x;
    int lane = tid & 31, warp = tid >> 5;
    int qg = lane >> 2, qt = lane & 3;
    int wm = warp >> 2, wn = warp & 3;

    uint32_t smb = smem_u32(sm);

    // producer A: row = tid&63, c4 = (tid>>6) + 4j, j in {0,1}  (8 floats/thread)
    int ar  = tid & 63;
    int ac4 = tid >> 6;
    bool av = (m0 + ar < cnt);
    const float* aptr = g_act + (Rbase + m0 + ar) * II + ac4 * 4;
    uint32_t asts0 = (uint32_t)(ar * (DN_LDA * 4) + ac4 * 16);
    uint32_t asts1 = asts0 + 64;          // +4 vec4 = +16 floats

    // producer B: row = tid>>3 (0..31), c4 = (tid&7) + 8j, j in 0..3 (16 floats)
    int br  = tid >> 3;
    int bc4 = tid & 7;
    const float* bptr = Wd + (size_t)br * HH + n0 + bc4 * 4;
    uint32_t bsts = (uint32_t)(br * 544 + bc4 * 16);

    const int NC = II / DN_BK;            // 24 chunks

    float4 rA0, rA1, rB[4];
    auto ldg = [&](int c) {
        size_t ko = (size_t)c * DN_BK;
        if (av) {
            rA0 = *(const float4*)(aptr + ko);
            rA1 = *(const float4*)(aptr + ko + 16);
        } else {
            rA0 = make_float4(0.f, 0.f, 0.f, 0.f);
            rA1 = rA0;
        }
        const float* b = bptr + ko * HH;
        #pragma unroll
        for (int j = 0; j < 4; j++)
            rB[j] = *(const float4*)(b + 32 * j);
    };
    auto sts = [&](int c) {
        uint32_t st = smb + (uint32_t)(c & 1) * DN_STAGE;
        sts128u(st + asts0, __float_as_uint(rA0.x), __float_as_uint(rA0.y),
                            __float_as_uint(rA0.z), __float_as_uint(rA0.w));
        sts128u(st + asts1, __float_as_uint(rA1.x), __float_as_uint(rA1.y),
                            __float_as_uint(rA1.z), __float_as_uint(rA1.w));
        uint32_t bb = st + DN_ASZ;
        #pragma unroll
        for (int j = 0; j < 4; j++)
            sts128u(bb + bsts + j * 128,
                    tf32r(rB[j].x), tf32r(rB[j].y), tf32r(rB[j].z), tf32r(rB[j].w));
    };

    float cc[2][4][4];
    #pragma unroll
    for (int mi = 0; mi < 2; mi++)
        #pragma unroll
        for (int ni = 0; ni < 4; ni++)
            #pragma unroll
            for (int r = 0; r < 4; r++) cc[mi][ni][r] = 0.f;

    ldg(0);
    for (int c = 0; c < NC; c++) {
        __syncthreads();
        sts(c);
        __syncthreads();
        if (c + 1 < NC) ldg(c + 1);

        const uint32_t* As = (const uint32_t*)(sm + (size_t)(c & 1) * DN_STAGE);
        const uint32_t* Bs = As + DN_ASZ / 4;

        #pragma unroll
        for (int kk = 0; kk < 4; kk++) {
            int kb = kk * 8;
            uint32_t a[2][4];
            #pragma unroll
            for (int mi = 0; mi < 2; mi++) {
                int r = wm * 32 + mi * 16 + qg;
                a[mi][0] = As[r * DN_LDA + kb + qt];
                a[mi][1] = As[(r + 8) * DN_LDA + kb + qt];
                a[mi][2] = As[r * DN_LDA + kb + qt + 4];
                a[mi][3] = As[(r + 8) * DN_LDA + kb + qt + 4];
            }
            uint32_t b[4][2];
            #pragma unroll
            for (int ni = 0; ni < 4; ni++) {
                int col = wn * 32 + ni * 8 + qg;
                b[ni][0] = Bs[(kb + qt) * 136 + col];
                b[ni][1] = Bs[(kb + qt + 4) * 136 + col];
            }
            #pragma unroll
            for (int mi = 0; mi < 2; mi++)
                #pragma unroll
                for (int ni = 0; ni < 4; ni++)
                    mma8(cc[mi][ni], a[mi], b[ni]);
        }
    }

    // ---- epilogue: out[tok] += wt * C (out pre-zeroed; shared uses wt=1) ----
    #pragma unroll
    for (int mi = 0; mi < 2; mi++) {
        #pragma unroll
        for (int h = 0; h < 2; h++) {
            int m = m0 + wm * 32 + mi * 16 + qg + 8 * h;
            if (m >= cnt) continue;
            int tok;
            float wt = 1.f;
            if (se) { tok = m; }
            else    { tok = g_tok[e * CAP + m]; wt = g_wt[e * CAP + m]; }
            float* dst = out + (size_t)tok * HH;
            #pragma unroll
            for (int ni = 0; ni < 4; ni++) {
                int col = n0 + wn * 32 + ni * 8 + qt * 2;
                atomicAdd(dst + col,     cc[mi][ni][2 * h] * wt);
                atomicAdd(dst + col + 1, cc[mi][ni][2 * h + 1] * wt);
            }
        }
    }
}

// ============================================================================
// launch
// ============================================================================
extern "C" void kernel_launch(void* const* d_in, const int* in_sizes, int n_in,
                              void* d_out, int out_size)
{
    const float* x       = (const float*)d_in[0];
    const float* gate_w  = (const float*)d_in[1];
    const float* gate_b  = (const float*)d_in[2];
    const float* w_gate  = (const float*)d_in[3];
    const float* w_up    = (const float*)d_in[4];
    const float* w_down  = (const float*)d_in[5];
    const float* sw_gate = (const float*)d_in[6];
    const float* sw_up   = (const float*)d_in[7];
    const float* sw_down = (const float*)d_in[8];
    float* out = (float*)d_out;

    // host-side, non-stream API: idempotent, executes immediately (capture-safe)
    cudaFuncSetAttribute(swiglu_kernel, cudaFuncAttributeMaxDynamicSharedMemorySize, SW_SMEM);
    cudaFuncSetAttribute(down_kernel,   cudaFuncAttributeMaxDynamicSharedMemorySize, DN_SMEM);

    zero_counts_kernel<<<1, 64>>>();
    cudaMemsetAsync(out, 0, sizeof(float) * (size_t)TT * HH);
    router_kernel<<<TT / 4, 256>>>(x, gate_w, gate_b);

    // routed experts (z<64) + shared expert (z==64)
    swiglu_kernel<<<dim3(II / NT, TT / MT, EE + 1), NTHR, SW_SMEM>>>(
        x, w_gate, w_up, sw_gate, sw_up);
    down_kernel<<<dim3(HH / NT, TT / MT, EE + 1), NTHR, DN_SMEM>>>(
        w_down, sw_down, out);
}